// round 15
// baseline (speedup 1.0000x reference)
#include <cuda_runtime.h>
#include <cuda_fp16.h>
#include <math.h>

typedef unsigned int u32;

#define ALPHA   8.3f
#define C_IN    64
#define C_OUT   64
#define H_IN    256
#define W_IN    256
#define H_OUT   254
#define W_OUT   254

#define NTHREADS 256
#define NCTAS    444                 // 148 SMs x 3 CTAs: exactly one wave
#define NT_TOTAL (4 * 4 * 127)       // b(4) x qstrip(4) x p-pair(127) = 2032 tiles

#define CPSTR    396                 // u32 stride per cpair = 6 ring rows x 66
// ---- smem layout (bytes) ----
#define OFF_BIAS 0                   // 64 f                 = 256
#define OFF_D    256                 // 6 x 66 f ring        = 1584 (pad to 1600)
#define OFF_DW   1856                // 9 x 128 f            = 4608
#define OFF_IMGH 6464                // 32 cpair x 396 u32   = 50688
#define SMEM_TOTAL 57152

__device__ __forceinline__ u32 packh2(float lo, float hi) {
    u32 r;
    asm("cvt.rn.f16x2.f32 %0, %1, %2;" : "=r"(r) : "f"(hi), "f"(lo));
    return r;
}
__device__ __forceinline__ u32 hmul2(u32 a, u32 b) {
    u32 r;
    asm("mul.rn.f16x2 %0, %1, %2;" : "=r"(r) : "r"(a), "r"(b));
    return r;
}

// mma.sync m16n8k16 fp16: D(16x8,f32) += A(16x16,f16) * B(16x8,f16)
#define MMA_F16(d, a0, a1, a2, a3, b0, b1)                                  \
    asm volatile(                                                           \
        "mma.sync.aligned.m16n8k16.row.col.f32.f16.f16.f32 "                \
        "{%0,%1,%2,%3}, {%4,%5,%6,%7}, {%8,%9}, {%0,%1,%2,%3};"             \
        : "+f"((d)[0]), "+f"((d)[1]), "+f"((d)[2]), "+f"((d)[3])            \
        : "r"(a0), "r"(a1), "r"(a2), "r"(a3), "r"(b0), "r"(b1))

// W pre-packed fp16 B-fragments: [kc16(36)][j(4)][lane(32)] uint4.
__device__ __align__(16) uint4 g_wh[36 * 4 * 32];

__global__ void prep_w(const float* __restrict__ w) {
    int idx = blockIdx.x * blockDim.x + threadIdx.x;
    if (idx >= 36 * 4 * 32) return;
    int lane = idx & 31;
    int j    = (idx >> 5) & 3;
    int kc16 = idx >> 7;
    int kl = kc16 >> 2, cq = kc16 & 3;
    int g = lane >> 2, t = lane & 3;
    int c0 = cq * 16 + 2 * t;
    int oce = (2 * j) * 8 + g;
    int oco = oce + 8;
    uint4 v;
    v.x = packh2(w[(oce * C_IN + c0)     * 9 + kl], w[(oce * C_IN + c0 + 1) * 9 + kl]);
    v.y = packh2(w[(oce * C_IN + c0 + 8) * 9 + kl], w[(oce * C_IN + c0 + 9) * 9 + kl]);
    v.z = packh2(w[(oco * C_IN + c0)     * 9 + kl], w[(oco * C_IN + c0 + 1) * 9 + kl]);
    v.w = packh2(w[(oco * C_IN + c0 + 8) * 9 + kl], w[(oco * C_IN + c0 + 9) * 9 + kl]);
    g_wh[idx] = v;
}

__global__ __launch_bounds__(NTHREADS, 3)
void depthconv_mma(const float* __restrict__ img,
                   const float* __restrict__ depth,
                   const float* __restrict__ bias,
                   float* __restrict__ out) {
    extern __shared__ char smem[];
    float* s_b    = (float*)(smem + OFF_BIAS);
    float* s_d    = (float*)(smem + OFF_D);     // 6-row depth ring
    float* s_dw   = (float*)(smem + OFF_DW);
    u32*   s_imgh = (u32*)  (smem + OFF_IMGH);  // [cpair(32)][slot(6)*66+cc]

    const int tid  = threadIdx.x;
    const int lane = tid & 31;
    const int wid  = tid >> 5;          // 8 warps: each 16 M-pixels x 64 oc
    const int g    = lane >> 2;
    const int t    = lane & 3;
    const int pr   = wid >> 2;          // output row within p-pair
    const int qw   = (wid & 3) * 16;    // q base of this warp's strip

    // static contiguous tile partition over exactly one wave of CTAs
    const int t_lo = (NT_TOTAL * (int)blockIdx.x) / NCTAS;
    const int t_hi = (NT_TOTAL * ((int)blockIdx.x + 1)) / NCTAS;

    if (tid < C_OUT) s_b[tid] = bias[tid];

    // decode first tile: tile = ((b*4 + s)*127 + pair)
    int tt   = t_lo;
    int b    = tt / 508;
    int rem  = tt - b * 508;
    int s    = rem / 127;
    int pair = rem - s * 127;
    bool fresh = true;

    const size_t HW = (size_t)H_IN * W_IN;

    for (; tt < t_hi; ++tt) {
        const int P  = 2 * pair;          // base output row (0..252)
        const int q0 = s * 64;
        const int qcnt = min(64, W_OUT - q0);

        // ---- stage img + depth rows [r0, r0+nr) into ring slots (row%6) ----
        {
            const int r0 = fresh ? P : P + 2;
            const int nr = fresh ? 4 : 2;
            const float* ip = img + (size_t)b * C_IN * HW;
            const int tot = nr * 66 * 32;
            for (int i = tid; i < tot; i += NTHREADS) {
                int cp  = i / (nr * 66);
                int r2  = i - cp * (nr * 66);
                int rr  = r2 / 66, cc = r2 - rr * 66;
                int row = r0 + rr;
                size_t go = ((size_t)(2 * cp) * H_IN + row) * W_IN +
                            min(q0 + cc, W_IN - 1);
                s_imgh[cp * CPSTR + (row % 6) * 66 + cc] =
                    packh2(ip[go], ip[go + HW]);
            }
            const float* dp = depth + (size_t)b * HW;
            for (int i = tid; i < nr * 66; i += NTHREADS) {
                int rr = i / 66, cc = i - rr * 66;
                int row = r0 + rr;
                s_d[(row % 6) * 66 + cc] = dp[row * W_IN + min(q0 + cc, W_IN - 1)];
            }
        }
        __syncthreads();

        // ---- dw[kl][m] from depth ring ----
        for (int i = tid; i < 1152; i += NTHREADS) {
            int kl = i >> 7, m = i & 127;
            int mpr = m >> 6, qq = m & 63;
            int k = kl / 3, l = kl - k * 3;
            float cen = s_d[((P + mpr + 1) % 6) * 66 + qq + 1];
            float val = s_d[((P + mpr + k) % 6) * 66 + qq + l];
            s_dw[i] = __expf(-ALPHA * fabsf(val - cen));
        }
        __syncthreads();

        float acc[8][4];
#pragma unroll
        for (int nb = 0; nb < 8; nb++)
#pragma unroll
            for (int rr = 0; rr < 4; rr++) acc[nb][rr] = 0.f;

        // per-warp ring row offsets for k = 0,1,2
        int sl0 = ((P + pr)     % 6) * 66;
        int sl1 = ((P + pr + 1) % 6) * 66;
        int sl2 = ((P + pr + 2) % 6) * 66;

        // ---- K loop: kl outer (not unrolled), cq inner x4 ----
        const uint4* wlane = g_wh + lane;
        for (int k = 0; k < 3; k++) {
            const int slk = (k == 0) ? sl0 : (k == 1) ? sl1 : sl2;
#pragma unroll 1
            for (int l = 0; l < 3; l++) {
                const int kl = k * 3 + l;
                const float* dwp = s_dw + kl * 128 + pr * 64 + qw;
                const u32 dwh0 = packh2(dwp[g],     dwp[g]);
                const u32 dwh1 = packh2(dwp[g + 8], dwp[g + 8]);
                const int pixbase = slk + l + qw;

#pragma unroll
                for (int cq = 0; cq < 4; cq++) {
                    const uint4* wf = wlane + (size_t)(kl * 4 + cq) * 128;
                    uint4 bq0 = __ldg(wf);
                    uint4 bq1 = __ldg(wf + 32);
                    uint4 bq2 = __ldg(wf + 64);
                    uint4 bq3 = __ldg(wf + 96);

                    const u32* pc  = s_imgh + (cq * 8 + t) * CPSTR + pixbase;
                    const u32* pc4 = pc + 4 * CPSTR;    // channels +8
                    u32 a0 = hmul2(pc [g],     dwh0);
                    u32 a1 = hmul2(pc [g + 8], dwh1);
                    u32 a2 = hmul2(pc4[g],     dwh0);
                    u32 a3 = hmul2(pc4[g + 8], dwh1);

                    MMA_F16(acc[0], a0, a1, a2, a3, bq0.x, bq0.y);
                    MMA_F16(acc[1], a0, a1, a2, a3, bq0.z, bq0.w);
                    MMA_F16(acc[2], a0, a1, a2, a3, bq1.x, bq1.y);
                    MMA_F16(acc[3], a0, a1, a2, a3, bq1.z, bq1.w);
                    MMA_F16(acc[4], a0, a1, a2, a3, bq2.x, bq2.y);
                    MMA_F16(acc[5], a0, a1, a2, a3, bq2.z, bq2.w);
                    MMA_F16(acc[6], a0, a1, a2, a3, bq3.x, bq3.y);
                    MMA_F16(acc[7], a0, a1, a2, a3, bq3.z, bq3.w);
                }
            }
        }

        // ---- epilogue: bias + store (no smem writes; no sync needed:
        //      next tile stages slots (P+4..P+5)%6, disjoint from P..P+3) ----
        const int qq0 = qw + g;
#pragma unroll
        for (int nb = 0; nb < 8; nb++) {
            const int oc = nb * 8 + t * 2;
            const float bs0 = s_b[oc], bs1 = s_b[oc + 1];
            const size_t base =
                (((size_t)b * C_OUT + oc) * H_OUT + (P + pr)) * W_OUT + q0;
            if (qq0 < qcnt) {
                out[base + qq0]                         = acc[nb][0] + bs0;
                out[base + (size_t)H_OUT * W_OUT + qq0] = acc[nb][1] + bs1;
            }
            if (qq0 + 8 < qcnt) {
                out[base + qq0 + 8]                         = acc[nb][2] + bs0;
                out[base + (size_t)H_OUT * W_OUT + qq0 + 8] = acc[nb][3] + bs1;
            }
        }

        // advance to next tile
        fresh = false;
        if (++pair == 127) {
            pair = 0;
            fresh = true;
            if (++s == 4) { s = 0; ++b; }
        }
    }
}

extern "C" void kernel_launch(void* const* d_in, const int* in_sizes, int n_in,
                              void* d_out, int out_size) {
    const float* img    = nullptr;
    const float* depth  = nullptr;
    const float* weight = nullptr;
    const float* bias   = nullptr;

    for (int i = 0; i < n_in; i++) {
        switch (in_sizes[i]) {
            case 4 * C_IN * H_IN * W_IN: img    = (const float*)d_in[i]; break;
            case 4 * 1 * H_IN * W_IN:    depth  = (const float*)d_in[i]; break;
            case C_OUT * C_IN * 9:       weight = (const float*)d_in[i]; break;
            case C_OUT:                  bias   = (const float*)d_in[i]; break;
            default: break;
        }
    }

    cudaFuncSetAttribute(depthconv_mma,
                         cudaFuncAttributeMaxDynamicSharedMemorySize, SMEM_TOTAL);

    prep_w<<<(36 * 4 * 32 + 255) / 256, 256>>>(weight);
    depthconv_mma<<<NCTAS, NTHREADS, SMEM_TOTAL>>>(img, depth, bias, (float*)d_out);
}